// round 2
// baseline (speedup 1.0000x reference)
#include <cuda_runtime.h>
#include <cuda_bf16.h>
#include <math_constants.h>

// Problem dims
#define BB 4
#define LL 4096
#define DM 1024
#define DD 128          // DK == DV == 128

// Scratch for projected q, k, v  (static device arrays: no runtime allocation)
__device__ float q_g[BB * LL * DD];
__device__ float k_g[BB * LL * DD];
__device__ float v_g[BB * LL * DD];

// ---------------------------------------------------------------------------
// Projection GEMM:  O[M=16384, N=128] = X[M, 1024] @ W[1024, 128]
// BM=64, BN=64, BK=16, 16x16 threads, 4x4 per thread.
// blockIdx.z selects which projection (Q/K/V).
// ---------------------------------------------------------------------------
__global__ __launch_bounds__(256)
void proj_kernel(const float* __restrict__ Qx, const float* __restrict__ Kx,
                 const float* __restrict__ Vx, const float* __restrict__ WQ,
                 const float* __restrict__ WK, const float* __restrict__ WV)
{
    __shared__ float As[16][65];   // [k][m], padded: conflict-free scalar reads
    __shared__ float Bs[16][64];   // [k][n], float4 reads

    const float* X;
    const float* W;
    float* O;
    if (blockIdx.z == 0)      { X = Qx; W = WQ; O = q_g; }
    else if (blockIdx.z == 1) { X = Kx; W = WK; O = k_g; }
    else                      { X = Vx; W = WV; O = v_g; }

    const int tx = threadIdx.x;          // 0..15
    const int ty = threadIdx.y;          // 0..15
    const int tid = ty * 16 + tx;

    const int row0 = blockIdx.y * 64;
    const int col0 = blockIdx.x * 64;

    // A loader: each thread loads 4 consecutive k's of one row
    const int ar  = tid >> 2;            // 0..63
    const int ac0 = (tid & 3) * 4;       // 0,4,8,12
    // B loader: each thread loads float4 of one k-row
    const int bk  = tid >> 4;            // 0..15
    const int bc0 = (tid & 15) * 4;      // 0..60

    float acc[4][4] = {};

    for (int kk = 0; kk < DM; kk += 16) {
        float4 a4 = *reinterpret_cast<const float4*>(
            X + (size_t)(row0 + ar) * DM + kk + ac0);
        As[ac0 + 0][ar] = a4.x;
        As[ac0 + 1][ar] = a4.y;
        As[ac0 + 2][ar] = a4.z;
        As[ac0 + 3][ar] = a4.w;

        *reinterpret_cast<float4*>(&Bs[bk][bc0]) =
            *reinterpret_cast<const float4*>(W + (size_t)(kk + bk) * DD + col0 + bc0);

        __syncthreads();

        #pragma unroll
        for (int k = 0; k < 16; k++) {
            const float a0 = As[k][ty * 4 + 0];
            const float a1 = As[k][ty * 4 + 1];
            const float a2 = As[k][ty * 4 + 2];
            const float a3 = As[k][ty * 4 + 3];
            const float4 b4 = *reinterpret_cast<const float4*>(&Bs[k][tx * 4]);
            acc[0][0] += a0 * b4.x; acc[0][1] += a0 * b4.y; acc[0][2] += a0 * b4.z; acc[0][3] += a0 * b4.w;
            acc[1][0] += a1 * b4.x; acc[1][1] += a1 * b4.y; acc[1][2] += a1 * b4.z; acc[1][3] += a1 * b4.w;
            acc[2][0] += a2 * b4.x; acc[2][1] += a2 * b4.y; acc[2][2] += a2 * b4.z; acc[2][3] += a2 * b4.w;
            acc[3][0] += a3 * b4.x; acc[3][1] += a3 * b4.y; acc[3][2] += a3 * b4.z; acc[3][3] += a3 * b4.w;
        }
        __syncthreads();
    }

    #pragma unroll
    for (int i = 0; i < 4; i++) {
        float4 o;
        o.x = acc[i][0]; o.y = acc[i][1]; o.z = acc[i][2]; o.w = acc[i][3];
        *reinterpret_cast<float4*>(
            O + (size_t)(row0 + ty * 4 + i) * DD + col0 + tx * 4) = o;
    }
}

// ---------------------------------------------------------------------------
// Flash attention (fp32, online softmax).
// Block: 256 threads, 128 queries (pair of threads splits D=128 into halves).
// Key tiles of BN=32 staged in shared; broadcast float4 reads.
// Mask applied BEFORE the 1/sqrt(dk) scale (as in the reference; -inf is
// invariant under scaling so the order is numerically identical).
// ---------------------------------------------------------------------------
#define BM 128
#define BN 32

__global__ __launch_bounds__(256, 1)
void attn_kernel(const int* __restrict__ mask, float* __restrict__ out)
{
    __shared__ float ks[BN][DD];
    __shared__ float vs[BN][DD];
    __shared__ int   msk[BN];

    const int tid   = threadIdx.x;
    const int qi    = tid >> 1;        // query within block: 0..127
    const int half  = tid & 1;         // which D-half this thread owns
    const int dbase = half * 64;
    const int b     = blockIdx.y;
    const int row   = blockIdx.x * BM + qi;

    // q row half in registers (16 x float4 = 64 floats)
    const float* qrow = q_g + ((size_t)(b * LL + row)) * DD + dbase;
    float4 qv[16];
    #pragma unroll
    for (int i = 0; i < 16; i++)
        qv[i] = reinterpret_cast<const float4*>(qrow)[i];

    float4 accv[16];
    #pragma unroll
    for (int i = 0; i < 16; i++) accv[i] = make_float4(0.f, 0.f, 0.f, 0.f);

    float m = -CUDART_INF_F;
    float l = 0.f;
    const float scale = 0.08838834764831845f;   // 1/sqrt(128)

    // tile loader coords: each thread loads 4 float4 (16 floats) per array
    const int j0 = tid >> 3;          // 0..31 (key row)
    const int d0 = (tid & 7) * 16;    // 0..112

    for (int kt = 0; kt < LL / BN; kt++) {
        const int kbase = kt * BN;
        {
            const float* kg = k_g + ((size_t)(b * LL + kbase + j0)) * DD + d0;
            const float* vg = v_g + ((size_t)(b * LL + kbase + j0)) * DD + d0;
            float4* ksd = reinterpret_cast<float4*>(&ks[j0][d0]);
            float4* vsd = reinterpret_cast<float4*>(&vs[j0][d0]);
            #pragma unroll
            for (int i = 0; i < 4; i++) {
                ksd[i] = reinterpret_cast<const float4*>(kg)[i];
                vsd[i] = reinterpret_cast<const float4*>(vg)[i];
            }
            if (tid < BN) msk[tid] = mask[b * LL + kbase + tid];
        }
        __syncthreads();

        // scores for this tile
        float s[BN];
        #pragma unroll
        for (int j = 0; j < BN; j++) {
            const float4* kp = reinterpret_cast<const float4*>(&ks[j][dbase]);
            float sum = 0.f;
            #pragma unroll
            for (int dd = 0; dd < 16; dd++) {
                const float4 k4 = kp[dd];
                sum += qv[dd].x * k4.x + qv[dd].y * k4.y
                     + qv[dd].z * k4.z + qv[dd].w * k4.w;
            }
            sum += __shfl_xor_sync(0xffffffffu, sum, 1);   // combine D-halves
            s[j] = msk[j] ? sum * scale : -CUDART_INF_F;
        }

        // online softmax update
        float tm = -CUDART_INF_F;
        #pragma unroll
        for (int j = 0; j < BN; j++) tm = fmaxf(tm, s[j]);
        const float mnew  = fmaxf(m, tm);
        const float msafe = (mnew == -CUDART_INF_F) ? 0.f : mnew;
        const float corr  = __expf(m - msafe);   // m=-inf -> 0 (acc empty)
        m = mnew;

        float lsum = 0.f;
        #pragma unroll
        for (int j = 0; j < BN; j++) {
            const float p = __expf(s[j] - msafe);
            s[j] = p;
            lsum += p;
        }
        l = l * corr + lsum;

        #pragma unroll
        for (int i = 0; i < 16; i++) {
            accv[i].x *= corr; accv[i].y *= corr;
            accv[i].z *= corr; accv[i].w *= corr;
        }

        #pragma unroll
        for (int j = 0; j < BN; j++) {
            const float p = s[j];
            const float4* vp = reinterpret_cast<const float4*>(&vs[j][dbase]);
            #pragma unroll
            for (int dd = 0; dd < 16; dd++) {
                const float4 v4 = vp[dd];
                accv[dd].x += p * v4.x; accv[dd].y += p * v4.y;
                accv[dd].z += p * v4.z; accv[dd].w += p * v4.w;
            }
        }
        __syncthreads();
    }

    const float inv = 1.f / l;
    float* orow = out + ((size_t)(b * LL + row)) * DD + dbase;
    #pragma unroll
    for (int i = 0; i < 16; i++) {
        float4 o;
        o.x = accv[i].x * inv; o.y = accv[i].y * inv;
        o.z = accv[i].z * inv; o.w = accv[i].w * inv;
        reinterpret_cast<float4*>(orow)[i] = o;
    }
}

// ---------------------------------------------------------------------------
// Launch
// ---------------------------------------------------------------------------
extern "C" void kernel_launch(void* const* d_in, const int* in_sizes, int n_in,
                              void* d_out, int out_size)
{
    const float* Q    = (const float*)d_in[0];
    const float* K    = (const float*)d_in[1];
    const float* V    = (const float*)d_in[2];
    const int*   mask = (const int*)  d_in[3];
    const float* WQ   = (const float*)d_in[4];
    const float* WK   = (const float*)d_in[5];
    const float* WV   = (const float*)d_in[6];
    float* out = (float*)d_out;

    dim3 pg(DD / 64, (BB * LL) / 64, 3);   // (2, 256, 3)
    proj_kernel<<<pg, dim3(16, 16)>>>(Q, K, V, WQ, WK, WV);

    dim3 ag(LL / BM, BB);                  // (32, 4)
    attn_kernel<<<ag, 256>>>(mask, out);
}

// round 4
// speedup vs baseline: 5.8157x; 5.8157x over previous
#include <cuda_runtime.h>
#include <cuda_bf16.h>
#include <math_constants.h>

#define BB 4
#define LL 4096
#define DM 1024
#define DD 128
#define SCALE 0.08838834764831845f

// ---------------- static device scratch ------------------------------------
__device__ float q_g[BB * LL * DD];
__device__ float k_g[BB * LL * DD];
__device__ float v_g[BB * LL * DD];
__device__ unsigned int k_hi[BB * LL * 64], k_lo[BB * LL * 64];   // bf16 pairs along d
__device__ unsigned int v_hi[BB * LL * 64], v_lo[BB * LL * 64];

// ---------------- helpers ---------------------------------------------------
__device__ __forceinline__ unsigned int smem_u32(const void* p) {
    unsigned int a;
    asm("{ .reg .u64 t; cvta.to.shared.u64 t, %1; cvt.u32.u64 %0, t; }" : "=r"(a) : "l"(p));
    return a;
}
__device__ __forceinline__ unsigned int pk2(float a, float b) {
    __nv_bfloat162 t = __floats2bfloat162_rn(a, b);
    return *reinterpret_cast<unsigned int*>(&t);
}
__device__ __forceinline__ void split2(float a, float b, unsigned int& h, unsigned int& l) {
    __nv_bfloat16 ah = __float2bfloat16(a), bh = __float2bfloat16(b);
    h = ((unsigned int)__bfloat16_as_ushort(bh) << 16) | __bfloat16_as_ushort(ah);
    l = pk2(a - __bfloat162float(ah), b - __bfloat162float(bh));
}
__device__ __forceinline__ void ldm4(unsigned int* r, unsigned int a) {
    asm volatile("ldmatrix.sync.aligned.m8n8.x4.shared.b16 {%0,%1,%2,%3}, [%4];"
                 : "=r"(r[0]), "=r"(r[1]), "=r"(r[2]), "=r"(r[3]) : "r"(a));
}
__device__ __forceinline__ void ldm4t(unsigned int* r, unsigned int a) {
    asm volatile("ldmatrix.sync.aligned.m8n8.x4.trans.shared.b16 {%0,%1,%2,%3}, [%4];"
                 : "=r"(r[0]), "=r"(r[1]), "=r"(r[2]), "=r"(r[3]) : "r"(a));
}
__device__ __forceinline__ void mma16816(float* d, const unsigned int* a, const unsigned int* b) {
    asm volatile("mma.sync.aligned.m16n8k16.row.col.f32.bf16.bf16.f32 "
                 "{%0,%1,%2,%3}, {%4,%5,%6,%7}, {%8,%9}, {%0,%1,%2,%3};"
                 : "+f"(d[0]), "+f"(d[1]), "+f"(d[2]), "+f"(d[3])
                 : "r"(a[0]), "r"(a[1]), "r"(a[2]), "r"(a[3]), "r"(b[0]), "r"(b[1]));
}

// ---------------------------------------------------------------------------
// Projection GEMM (scalar, known-good)
// ---------------------------------------------------------------------------
__global__ __launch_bounds__(256)
void proj_kernel(const float* __restrict__ Qx, const float* __restrict__ Kx,
                 const float* __restrict__ Vx, const float* __restrict__ WQ,
                 const float* __restrict__ WK, const float* __restrict__ WV)
{
    __shared__ float As[16][65];
    __shared__ float Bs[16][64];
    const float* X; const float* W; float* O;
    if (blockIdx.z == 0)      { X = Qx; W = WQ; O = q_g; }
    else if (blockIdx.z == 1) { X = Kx; W = WK; O = k_g; }
    else                      { X = Vx; W = WV; O = v_g; }

    const int tx = threadIdx.x, ty = threadIdx.y;
    const int tid = ty * 16 + tx;
    const int row0 = blockIdx.y * 64, col0 = blockIdx.x * 64;
    const int ar = tid >> 2, ac0 = (tid & 3) * 4;
    const int bk = tid >> 4, bc0 = (tid & 15) * 4;

    float acc[4][4] = {};
    for (int kk = 0; kk < DM; kk += 16) {
        float4 a4 = *reinterpret_cast<const float4*>(X + (size_t)(row0 + ar) * DM + kk + ac0);
        As[ac0 + 0][ar] = a4.x; As[ac0 + 1][ar] = a4.y;
        As[ac0 + 2][ar] = a4.z; As[ac0 + 3][ar] = a4.w;
        *reinterpret_cast<float4*>(&Bs[bk][bc0]) =
            *reinterpret_cast<const float4*>(W + (size_t)(kk + bk) * DD + col0 + bc0);
        __syncthreads();
        #pragma unroll
        for (int k = 0; k < 16; k++) {
            const float a0 = As[k][ty * 4 + 0], a1 = As[k][ty * 4 + 1];
            const float a2 = As[k][ty * 4 + 2], a3 = As[k][ty * 4 + 3];
            const float4 b4 = *reinterpret_cast<const float4*>(&Bs[k][tx * 4]);
            acc[0][0] += a0 * b4.x; acc[0][1] += a0 * b4.y; acc[0][2] += a0 * b4.z; acc[0][3] += a0 * b4.w;
            acc[1][0] += a1 * b4.x; acc[1][1] += a1 * b4.y; acc[1][2] += a1 * b4.z; acc[1][3] += a1 * b4.w;
            acc[2][0] += a2 * b4.x; acc[2][1] += a2 * b4.y; acc[2][2] += a2 * b4.z; acc[2][3] += a2 * b4.w;
            acc[3][0] += a3 * b4.x; acc[3][1] += a3 * b4.y; acc[3][2] += a3 * b4.z; acc[3][3] += a3 * b4.w;
        }
        __syncthreads();
    }
    #pragma unroll
    for (int i = 0; i < 4; i++) {
        float4 o; o.x = acc[i][0]; o.y = acc[i][1]; o.z = acc[i][2]; o.w = acc[i][3];
        *reinterpret_cast<float4*>(O + (size_t)(row0 + ty * 4 + i) * DD + col0 + tx * 4) = o;
    }
}

// ---------------------------------------------------------------------------
// Pack K and V to bf16 hi/lo pairs
// ---------------------------------------------------------------------------
__global__ __launch_bounds__(256)
void conv_kernel()
{
    const int i = blockIdx.x * 256 + threadIdx.x;   // < BB*LL*64
    const float2 xk = reinterpret_cast<const float2*>(k_g)[i];
    const float2 xv = reinterpret_cast<const float2*>(v_g)[i];
    unsigned int h, l;
    split2(xk.x, xk.y, h, l); k_hi[i] = h; k_lo[i] = l;
    split2(xv.x, xv.y, h, l); v_hi[i] = h; v_lo[i] = l;
}

// ---------------------------------------------------------------------------
// Fused flash attention with mma.sync bf16x3
// smem layout (bytes): KHI 0, KLO 17408, VHI 34816, VLO 52224, MSKF 69632
// Q staging reuses [0, 69632); output staging reuses [0, 67584)
// ---------------------------------------------------------------------------
#define KHI 0
#define KLO 17408
#define VHI 34816
#define VLO 52224
#define MSKF 69632
#define SMEM_BYTES 69888

__global__ __launch_bounds__(256, 1)
void attn_kernel(const int* __restrict__ mask, float* __restrict__ out)
{
    extern __shared__ char sm[];
    const unsigned int sb = smem_u32(sm);
    const int tid = threadIdx.x, w = tid >> 5, lane = tid & 31;
    const int lr = lane & 7, g = lane >> 3, qd = lane & 3, rowA = lane >> 2;
    const int qt = blockIdx.x, b = blockIdx.y;

    // ---- stage & fragment Q (persistent in registers) ----
    const float* qsrc = q_g + ((size_t)(b * LL + qt * 128)) * DD;
    for (int i = tid; i < 128 * 64; i += 256) {
        const int r = i >> 6, p = i & 63;
        const float2 x = reinterpret_cast<const float2*>(qsrc)[i];
        unsigned int h, l; split2(x.x, x.y, h, l);
        *reinterpret_cast<unsigned int*>(sm + r * 272 + p * 4) = h;
        *reinterpret_cast<unsigned int*>(sm + 34816 + r * 272 + p * 4) = l;
    }
    __syncthreads();
    unsigned int qh[8][4], ql[8][4];
    {
        const int row = 16 * w + lr + ((g & 1) ? 8 : 0);
        #pragma unroll
        for (int s = 0; s < 8; s++) {
            const int col = 16 * s + ((g & 2) ? 8 : 0);
            const unsigned int a = sb + (row * 136 + col) * 2;
            ldm4(qh[s], a);
            ldm4(ql[s], a + 34816);
        }
    }
    __syncthreads();

    float oacc[16][4];
    #pragma unroll
    for (int j = 0; j < 16; j++)
        { oacc[j][0] = 0.f; oacc[j][1] = 0.f; oacc[j][2] = 0.f; oacc[j][3] = 0.f; }
    float m0 = -CUDART_INF_F, m1 = -CUDART_INF_F, l0 = 0.f, l1 = 0.f;

    const uint4* khi4 = reinterpret_cast<const uint4*>(k_hi) + (size_t)b * LL * 16;
    const uint4* klo4 = reinterpret_cast<const uint4*>(k_lo) + (size_t)b * LL * 16;
    const uint4* vhi4 = reinterpret_cast<const uint4*>(v_hi) + (size_t)b * LL * 16;
    const uint4* vlo4 = reinterpret_cast<const uint4*>(v_lo) + (size_t)b * LL * 16;

    for (int kt = 0; kt < 64; kt++) {
        // ---- stage K/V tile (64 keys x 128 dims, hi/lo) ----
        for (int i = tid; i < 1024; i += 256) {
            const int key = i >> 4, j = i & 15;
            const size_t gi = (size_t)(kt * 64 + key) * 16 + j;
            const int so = key * 272 + j * 16;
            *reinterpret_cast<uint4*>(sm + KHI + so) = khi4[gi];
            *reinterpret_cast<uint4*>(sm + KLO + so) = klo4[gi];
            *reinterpret_cast<uint4*>(sm + VHI + so) = vhi4[gi];
            *reinterpret_cast<uint4*>(sm + VLO + so) = vlo4[gi];
        }
        if (tid < 64)
            reinterpret_cast<float*>(sm + MSKF)[tid] =
                mask[b * LL + kt * 64 + tid] ? 0.f : -CUDART_INF_F;
        __syncthreads();

        // ---- S = Q . K^T (bf16x3) ----
        float sacc[8][4];
        #pragma unroll
        for (int j = 0; j < 8; j++)
            { sacc[j][0] = 0.f; sacc[j][1] = 0.f; sacc[j][2] = 0.f; sacc[j][3] = 0.f; }
        #pragma unroll
        for (int s = 0; s < 8; s++) {
            #pragma unroll
            for (int j2 = 0; j2 < 4; j2++) {
                const int row = 16 * j2 + lr + ((g & 2) ? 8 : 0);
                const int col = 16 * s + ((g & 1) ? 8 : 0);
                const unsigned int a = sb + KHI + (row * 136 + col) * 2;
                unsigned int bh[4], bl[4];
                ldm4(bh, a);
                ldm4(bl, a + (KLO - KHI));
                mma16816(sacc[2 * j2],     qh[s], bh);
                mma16816(sacc[2 * j2],     qh[s], bl);
                mma16816(sacc[2 * j2],     ql[s], bh);
                mma16816(sacc[2 * j2 + 1], qh[s], bh + 2);
                mma16816(sacc[2 * j2 + 1], qh[s], bl + 2);
                mma16816(sacc[2 * j2 + 1], ql[s], bh + 2);
            }
        }

        // ---- mask + scale + online softmax (in fragments) ----
        const float* mskf = reinterpret_cast<const float*>(sm + MSKF);
        float t0 = -CUDART_INF_F, t1 = -CUDART_INF_F;
        #pragma unroll
        for (int j = 0; j < 8; j++) {
            const float ma = mskf[8 * j + 2 * qd], mb = mskf[8 * j + 2 * qd + 1];
            sacc[j][0] = sacc[j][0] * SCALE + ma;
            sacc[j][1] = sacc[j][1] * SCALE + mb;
            sacc[j][2] = sacc[j][2] * SCALE + ma;
            sacc[j][3] = sacc[j][3] * SCALE + mb;
            t0 = fmaxf(t0, fmaxf(sacc[j][0], sacc[j][1]));
            t1 = fmaxf(t1, fmaxf(sacc[j][2], sacc[j][3]));
        }
        t0 = fmaxf(t0, __shfl_xor_sync(0xffffffffu, t0, 1));
        t0 = fmaxf(t0, __shfl_xor_sync(0xffffffffu, t0, 2));
        t1 = fmaxf(t1, __shfl_xor_sync(0xffffffffu, t1, 1));
        t1 = fmaxf(t1, __shfl_xor_sync(0xffffffffu, t1, 2));
        const float mn0 = fmaxf(m0, t0), mn1 = fmaxf(m1, t1);
        const float ms0 = (mn0 == -CUDART_INF_F) ? 0.f : mn0;
        const float ms1 = (mn1 == -CUDART_INF_F) ? 0.f : mn1;
        const float c0 = __expf(m0 - ms0), c1 = __expf(m1 - ms1);
        m0 = mn0; m1 = mn1;
        float rs0 = 0.f, rs1 = 0.f;
        #pragma unroll
        for (int j = 0; j < 8; j++) {
            sacc[j][0] = __expf(sacc[j][0] - ms0); rs0 += sacc[j][0];
            sacc[j][1] = __expf(sacc[j][1] - ms0); rs0 += sacc[j][1];
            sacc[j][2] = __expf(sacc[j][2] - ms1); rs1 += sacc[j][2];
            sacc[j][3] = __expf(sacc[j][3] - ms1); rs1 += sacc[j][3];
        }
        l0 = l0 * c0 + rs0;
        l1 = l1 * c1 + rs1;
        #pragma unroll
        for (int j = 0; j < 16; j++) {
            oacc[j][0] *= c0; oacc[j][1] *= c0;
            oacc[j][2] *= c1; oacc[j][3] *= c1;
        }

        // ---- P fragments (bf16 hi/lo), directly from S fragments ----
        unsigned int pah[4][4], pal[4][4];
        #pragma unroll
        for (int kk = 0; kk < 4; kk++) {
            split2(sacc[2 * kk][0],     sacc[2 * kk][1],     pah[kk][0], pal[kk][0]);
            split2(sacc[2 * kk][2],     sacc[2 * kk][3],     pah[kk][1], pal[kk][1]);
            split2(sacc[2 * kk + 1][0], sacc[2 * kk + 1][1], pah[kk][2], pal[kk][2]);
            split2(sacc[2 * kk + 1][2], sacc[2 * kk + 1][3], pah[kk][3], pal[kk][3]);
        }

        // ---- O += P . V (bf16x3, ldmatrix.trans on V) ----
        #pragma unroll
        for (int kk = 0; kk < 4; kk++) {
            #pragma unroll
            for (int j2 = 0; j2 < 8; j2++) {
                const int row = 16 * kk + lr + ((g & 1) ? 8 : 0);
                const int col = 16 * j2 + ((g & 2) ? 8 : 0);
                const unsigned int a = sb + VHI + (row * 136 + col) * 2;
                unsigned int bh[4], bl[4];
                ldm4t(bh, a);
                ldm4t(bl, a + (VLO - VHI));
                mma16816(oacc[2 * j2],     pah[kk], bh);
                mma16816(oacc[2 * j2],     pah[kk], bl);
                mma16816(oacc[2 * j2],     pal[kk], bh);
                mma16816(oacc[2 * j2 + 1], pah[kk], bh + 2);
                mma16816(oacc[2 * j2 + 1], pah[kk], bl + 2);
                mma16816(oacc[2 * j2 + 1], pal[kk], bh + 2);
            }
        }
        __syncthreads();
    }

    // ---- epilogue: 1/l, smem transpose, coalesced store ----
    l0 += __shfl_xor_sync(0xffffffffu, l0, 1);
    l0 += __shfl_xor_sync(0xffffffffu, l0, 2);
    l1 += __shfl_xor_sync(0xffffffffu, l1, 1);
    l1 += __shfl_xor_sync(0xffffffffu, l1, 2);
    const float i0 = (l0 > 0.f) ? 1.f / l0 : 0.f;
    const float i1 = (l1 > 0.f) ? 1.f / l1 : 0.f;

    float* os = reinterpret_cast<float*>(sm);
    const int r0 = 16 * w + rowA;
    #pragma unroll
    for (int j = 0; j < 16; j++) {
        const int c = 8 * j + 2 * qd;
        os[r0 * 132 + c]           = oacc[j][0] * i0;
        os[r0 * 132 + c + 1]       = oacc[j][1] * i0;
        os[(r0 + 8) * 132 + c]     = oacc[j][2] * i1;
        os[(r0 + 8) * 132 + c + 1] = oacc[j][3] * i1;
    }
    __syncthreads();
    float* og = out + ((size_t)(b * LL + qt * 128)) * DD;
    for (int i = tid; i < 128 * 32; i += 256) {
        const int r = i >> 5, j = i & 31;
        *reinterpret_cast<float4*>(og + r * 128 + 4 * j) =
            *reinterpret_cast<const float4*>(os + r * 132 + 4 * j);
    }
}

// ---------------------------------------------------------------------------
// Launch
// ---------------------------------------------------------------------------
extern "C" void kernel_launch(void* const* d_in, const int* in_sizes, int n_in,
                              void* d_out, int out_size)
{
    const float* Q    = (const float*)d_in[0];
    const float* K    = (const float*)d_in[1];
    const float* V    = (const float*)d_in[2];
    const int*   mask = (const int*)  d_in[3];
    const float* WQ   = (const float*)d_in[4];
    const float* WK   = (const float*)d_in[5];
    const float* WV   = (const float*)d_in[6];
    float* out = (float*)d_out;

    cudaFuncSetAttribute(attn_kernel, cudaFuncAttributeMaxDynamicSharedMemorySize, SMEM_BYTES);

    dim3 pg(DD / 64, (BB * LL) / 64, 3);
    proj_kernel<<<pg, dim3(16, 16)>>>(Q, K, V, WQ, WK, WV);

    conv_kernel<<<BB * LL * 64 / 256, 256>>>();

    attn_kernel<<<dim3(32, BB), 256, SMEM_BYTES>>>(mask, out);
}

// round 5
// speedup vs baseline: 6.1377x; 1.0554x over previous
#include <cuda_runtime.h>
#include <cuda_bf16.h>
#include <math_constants.h>

#define BB 4
#define LL 4096
#define DM 1024
#define DD 128
#define SCALE 0.08838834764831845f

// ---------------- static device scratch (packed bf16 hi/lo pairs) -----------
__device__ unsigned int q_hi[BB * LL * 64], q_lo[BB * LL * 64];
__device__ unsigned int k_hi[BB * LL * 64], k_lo[BB * LL * 64];
__device__ unsigned int v_hi[BB * LL * 64], v_lo[BB * LL * 64];
__device__ unsigned int wt_hi[3 * 128 * 512], wt_lo[3 * 128 * 512];  // W^T packed

// ---------------- helpers ---------------------------------------------------
__device__ __forceinline__ unsigned int smem_u32(const void* p) {
    unsigned int a;
    asm("{ .reg .u64 t; cvta.to.shared.u64 t, %1; cvt.u32.u64 %0, t; }" : "=r"(a) : "l"(p));
    return a;
}
__device__ __forceinline__ unsigned int pk2(float a, float b) {
    __nv_bfloat162 t = __floats2bfloat162_rn(a, b);
    return *reinterpret_cast<unsigned int*>(&t);
}
__device__ __forceinline__ void split2(float a, float b, unsigned int& h, unsigned int& l) {
    __nv_bfloat16 ah = __float2bfloat16(a), bh = __float2bfloat16(b);
    h = ((unsigned int)__bfloat16_as_ushort(bh) << 16) | __bfloat16_as_ushort(ah);
    l = pk2(a - __bfloat162float(ah), b - __bfloat162float(bh));
}
__device__ __forceinline__ void ldm4(unsigned int* r, unsigned int a) {
    asm volatile("ldmatrix.sync.aligned.m8n8.x4.shared.b16 {%0,%1,%2,%3}, [%4];"
                 : "=r"(r[0]), "=r"(r[1]), "=r"(r[2]), "=r"(r[3]) : "r"(a));
}
__device__ __forceinline__ void ldm4t(unsigned int* r, unsigned int a) {
    asm volatile("ldmatrix.sync.aligned.m8n8.x4.trans.shared.b16 {%0,%1,%2,%3}, [%4];"
                 : "=r"(r[0]), "=r"(r[1]), "=r"(r[2]), "=r"(r[3]) : "r"(a));
}
__device__ __forceinline__ void mma16816(float* d, const unsigned int* a, const unsigned int* b) {
    asm volatile("mma.sync.aligned.m16n8k16.row.col.f32.bf16.bf16.f32 "
                 "{%0,%1,%2,%3}, {%4,%5,%6,%7}, {%8,%9}, {%0,%1,%2,%3};"
                 : "+f"(d[0]), "+f"(d[1]), "+f"(d[2]), "+f"(d[3])
                 : "r"(a[0]), "r"(a[1]), "r"(a[2]), "r"(a[3]), "r"(b[0]), "r"(b[1]));
}

// ---------------------------------------------------------------------------
// W^T pack: W[k][n] fp32 -> wt[n][kpair] bf16 hi/lo
// ---------------------------------------------------------------------------
__global__ __launch_bounds__(256)
void wconv_kernel(const float* __restrict__ WQ, const float* __restrict__ WK,
                  const float* __restrict__ WV)
{
    const int gid = blockIdx.x * 256 + threadIdx.x;      // < 3*65536
    const int t = gid >> 16, i = gid & 65535;
    const int n = i & 127, kp = i >> 7;
    const float* W = (t == 0) ? WQ : (t == 1) ? WK : WV;
    unsigned int h, l;
    split2(W[(2 * kp) * 128 + n], W[(2 * kp + 1) * 128 + n], h, l);
    wt_hi[t * 65536 + n * 512 + kp] = h;
    wt_lo[t * 65536 + n * 512 + kp] = l;
}

// ---------------------------------------------------------------------------
// Projection via mma.sync bf16x3:  O[16384,128] = X[16384,1024] @ W[1024,128]
// CTA: 128 rows x 128 cols, K-chunks of 64. Outputs packed bf16 hi/lo pairs.
// smem: XHI 0, XLO 18432, WHI 36864, WLO 55296 (144B row stride, conflict-free)
// ---------------------------------------------------------------------------
#define PX_HI 0
#define PX_LO 18432
#define PW_HI 36864
#define PW_LO 55296
#define P_SMEM 73728

__global__ __launch_bounds__(256)
void proj_mma_kernel(const float* __restrict__ Qx, const float* __restrict__ Kx,
                     const float* __restrict__ Vx)
{
    extern __shared__ char sm[];
    const unsigned int sb = smem_u32(sm);
    const int tid = threadIdx.x, w = tid >> 5, lane = tid & 31;
    const int lr = lane & 7, g = lane >> 3, qd = lane & 3, rowA = lane >> 2;
    const int mt = blockIdx.x, t = blockIdx.y;

    const float* X = (t == 0) ? Qx : (t == 1) ? Kx : Vx;
    const unsigned int* WH = wt_hi + t * 65536;
    const unsigned int* WL = wt_lo + t * 65536;
    unsigned int* OH = (t == 0) ? q_hi : (t == 1) ? k_hi : v_hi;
    unsigned int* OL = (t == 0) ? q_lo : (t == 1) ? k_lo : v_lo;

    const int row0 = mt * 128;
    float acc[16][4] = {};

    for (int kk = 0; kk < DM; kk += 64) {
        // stage X chunk: 128 rows x 32 pairs (fp32 -> bf16 hi/lo)
        for (int i = tid; i < 4096; i += 256) {
            const int r = i >> 5, p = i & 31;
            const float2 x = reinterpret_cast<const float2*>(X)
                [(size_t)(row0 + r) * 512 + (kk >> 1) + p];
            unsigned int h, l; split2(x.x, x.y, h, l);
            *reinterpret_cast<unsigned int*>(sm + PX_HI + r * 144 + p * 4) = h;
            *reinterpret_cast<unsigned int*>(sm + PX_LO + r * 144 + p * 4) = l;
        }
        // stage W^T chunk: 128 n-rows x 32 pairs (already packed)
        for (int i = tid; i < 4096; i += 256) {
            const int n = i >> 5, p = i & 31;
            const int src = n * 512 + (kk >> 1) + p;
            *reinterpret_cast<unsigned int*>(sm + PW_HI + n * 144 + p * 4) = WH[src];
            *reinterpret_cast<unsigned int*>(sm + PW_LO + n * 144 + p * 4) = WL[src];
        }
        __syncthreads();

        unsigned int ah[4][4], al[4][4];
        #pragma unroll
        for (int s = 0; s < 4; s++) {
            const int row = 16 * w + lr + ((g & 1) ? 8 : 0);
            const int col = 16 * s + ((g & 2) ? 8 : 0);
            const unsigned int a = sb + PX_HI + row * 144 + col * 2;
            ldm4(ah[s], a);
            ldm4(al[s], a + (PX_LO - PX_HI));
        }
        #pragma unroll
        for (int s = 0; s < 4; s++) {
            #pragma unroll
            for (int j2 = 0; j2 < 8; j2++) {
                const int row = 16 * j2 + lr + ((g & 2) ? 8 : 0);
                const int col = 16 * s + ((g & 1) ? 8 : 0);
                const unsigned int a = sb + PW_HI + row * 144 + col * 2;
                unsigned int bh[4], bl[4];
                ldm4(bh, a);
                ldm4(bl, a + (PW_LO - PW_HI));
                mma16816(acc[2 * j2],     ah[s], bh);
                mma16816(acc[2 * j2],     ah[s], bl);
                mma16816(acc[2 * j2],     al[s], bh);
                mma16816(acc[2 * j2 + 1], ah[s], bh + 2);
                mma16816(acc[2 * j2 + 1], ah[s], bl + 2);
                mma16816(acc[2 * j2 + 1], al[s], bh + 2);
            }
        }
        __syncthreads();
    }

    // epilogue: pack fragment col-pairs -> global hi/lo
    const int r0 = row0 + 16 * w + rowA;
    #pragma unroll
    for (int j = 0; j < 16; j++) {
        const int pi = 4 * j + qd;
        unsigned int h, l;
        split2(acc[j][0], acc[j][1], h, l);
        OH[(size_t)r0 * 64 + pi] = h;
        OL[(size_t)r0 * 64 + pi] = l;
        split2(acc[j][2], acc[j][3], h, l);
        OH[(size_t)(r0 + 8) * 64 + pi] = h;
        OL[(size_t)(r0 + 8) * 64 + pi] = l;
    }
}

// ---------------------------------------------------------------------------
// Fused flash attention with mma.sync bf16x3 (unchanged core from R4)
// ---------------------------------------------------------------------------
#define KHI 0
#define KLO 17408
#define VHI 34816
#define VLO 52224
#define MSKF 69632
#define SMEM_BYTES 69888

__global__ __launch_bounds__(256, 1)
void attn_kernel(const int* __restrict__ mask, float* __restrict__ out)
{
    extern __shared__ char sm[];
    const unsigned int sb = smem_u32(sm);
    const int tid = threadIdx.x, w = tid >> 5, lane = tid & 31;
    const int lr = lane & 7, g = lane >> 3, qd = lane & 3, rowA = lane >> 2;
    const int qt = blockIdx.x, b = blockIdx.y;

    // ---- stage & fragment Q (packed hi/lo, persistent in registers) ----
    const unsigned int* qhs = q_hi + (size_t)(b * LL + qt * 128) * 64;
    const unsigned int* qls = q_lo + (size_t)(b * LL + qt * 128) * 64;
    for (int i = tid; i < 128 * 64; i += 256) {
        const int r = i >> 6, p = i & 63;
        *reinterpret_cast<unsigned int*>(sm + r * 272 + p * 4) = qhs[i];
        *reinterpret_cast<unsigned int*>(sm + 34816 + r * 272 + p * 4) = qls[i];
    }
    __syncthreads();
    unsigned int qh[8][4], ql[8][4];
    {
        const int row = 16 * w + lr + ((g & 1) ? 8 : 0);
        #pragma unroll
        for (int s = 0; s < 8; s++) {
            const int col = 16 * s + ((g & 2) ? 8 : 0);
            const unsigned int a = sb + (row * 136 + col) * 2;
            ldm4(qh[s], a);
            ldm4(ql[s], a + 34816);
        }
    }
    __syncthreads();

    float oacc[16][4];
    #pragma unroll
    for (int j = 0; j < 16; j++)
        { oacc[j][0] = 0.f; oacc[j][1] = 0.f; oacc[j][2] = 0.f; oacc[j][3] = 0.f; }
    float m0 = -CUDART_INF_F, m1 = -CUDART_INF_F, l0 = 0.f, l1 = 0.f;

    const uint4* khi4 = reinterpret_cast<const uint4*>(k_hi) + (size_t)b * LL * 16;
    const uint4* klo4 = reinterpret_cast<const uint4*>(k_lo) + (size_t)b * LL * 16;
    const uint4* vhi4 = reinterpret_cast<const uint4*>(v_hi) + (size_t)b * LL * 16;
    const uint4* vlo4 = reinterpret_cast<const uint4*>(v_lo) + (size_t)b * LL * 16;

    for (int kt = 0; kt < 64; kt++) {
        for (int i = tid; i < 1024; i += 256) {
            const int key = i >> 4, j = i & 15;
            const size_t gi = (size_t)(kt * 64 + key) * 16 + j;
            const int so = key * 272 + j * 16;
            *reinterpret_cast<uint4*>(sm + KHI + so) = khi4[gi];
            *reinterpret_cast<uint4*>(sm + KLO + so) = klo4[gi];
            *reinterpret_cast<uint4*>(sm + VHI + so) = vhi4[gi];
            *reinterpret_cast<uint4*>(sm + VLO + so) = vlo4[gi];
        }
        if (tid < 64)
            reinterpret_cast<float*>(sm + MSKF)[tid] =
                mask[b * LL + kt * 64 + tid] ? 0.f : -CUDART_INF_F;
        __syncthreads();

        float sacc[8][4];
        #pragma unroll
        for (int j = 0; j < 8; j++)
            { sacc[j][0] = 0.f; sacc[j][1] = 0.f; sacc[j][2] = 0.f; sacc[j][3] = 0.f; }
        #pragma unroll
        for (int s = 0; s < 8; s++) {
            #pragma unroll
            for (int j2 = 0; j2 < 4; j2++) {
                const int row = 16 * j2 + lr + ((g & 2) ? 8 : 0);
                const int col = 16 * s + ((g & 1) ? 8 : 0);
                const unsigned int a = sb + KHI + (row * 136 + col) * 2;
                unsigned int bh[4], bl[4];
                ldm4(bh, a);
                ldm4(bl, a + (KLO - KHI));
                mma16816(sacc[2 * j2],     qh[s], bh);
                mma16816(sacc[2 * j2],     qh[s], bl);
                mma16816(sacc[2 * j2],     ql[s], bh);
                mma16816(sacc[2 * j2 + 1], qh[s], bh + 2);
                mma16816(sacc[2 * j2 + 1], qh[s], bl + 2);
                mma16816(sacc[2 * j2 + 1], ql[s], bh + 2);
            }
        }

        const float* mskf = reinterpret_cast<const float*>(sm + MSKF);
        float t0 = -CUDART_INF_F, t1 = -CUDART_INF_F;
        #pragma unroll
        for (int j = 0; j < 8; j++) {
            const float ma = mskf[8 * j + 2 * qd], mb = mskf[8 * j + 2 * qd + 1];
            sacc[j][0] = sacc[j][0] * SCALE + ma;
            sacc[j][1] = sacc[j][1] * SCALE + mb;
            sacc[j][2] = sacc[j][2] * SCALE + ma;
            sacc[j][3] = sacc[j][3] * SCALE + mb;
            t0 = fmaxf(t0, fmaxf(sacc[j][0], sacc[j][1]));
            t1 = fmaxf(t1, fmaxf(sacc[j][2], sacc[j][3]));
        }
        t0 = fmaxf(t0, __shfl_xor_sync(0xffffffffu, t0, 1));
        t0 = fmaxf(t0, __shfl_xor_sync(0xffffffffu, t0, 2));
        t1 = fmaxf(t1, __shfl_xor_sync(0xffffffffu, t1, 1));
        t1 = fmaxf(t1, __shfl_xor_sync(0xffffffffu, t1, 2));
        const float mn0 = fmaxf(m0, t0), mn1 = fmaxf(m1, t1);
        const float ms0 = (mn0 == -CUDART_INF_F) ? 0.f : mn0;
        const float ms1 = (mn1 == -CUDART_INF_F) ? 0.f : mn1;
        const float c0 = __expf(m0 - ms0), c1 = __expf(m1 - ms1);
        m0 = mn0; m1 = mn1;
        float rs0 = 0.f, rs1 = 0.f;
        #pragma unroll
        for (int j = 0; j < 8; j++) {
            sacc[j][0] = __expf(sacc[j][0] - ms0); rs0 += sacc[j][0];
            sacc[j][1] = __expf(sacc[j][1] - ms0); rs0 += sacc[j][1];
            sacc[j][2] = __expf(sacc[j][2] - ms1); rs1 += sacc[j][2];
            sacc[j][3] = __expf(sacc[j][3] - ms1); rs1 += sacc[j][3];
        }
        l0 = l0 * c0 + rs0;
        l1 = l1 * c1 + rs1;
        #pragma unroll
        for (int j = 0; j < 16; j++) {
            oacc[j][0] *= c0; oacc[j][1] *= c0;
            oacc[j][2] *= c1; oacc[j][3] *= c1;
        }

        unsigned int pah[4][4], pal[4][4];
        #pragma unroll
        for (int kk = 0; kk < 4; kk++) {
            split2(sacc[2 * kk][0],     sacc[2 * kk][1],     pah[kk][0], pal[kk][0]);
            split2(sacc[2 * kk][2],     sacc[2 * kk][3],     pah[kk][1], pal[kk][1]);
            split2(sacc[2 * kk + 1][0], sacc[2 * kk + 1][1], pah[kk][2], pal[kk][2]);
            split2(sacc[2 * kk + 1][2], sacc[2 * kk + 1][3], pah[kk][3], pal[kk][3]);
        }

        #pragma unroll
        for (int kk = 0; kk < 4; kk++) {
            #pragma unroll
            for (int j2 = 0; j2 < 8; j2++) {
                const int row = 16 * kk + lr + ((g & 1) ? 8 : 0);
                const int col = 16 * j2 + ((g & 2) ? 8 : 0);
                const unsigned int a = sb + VHI + (row * 136 + col) * 2;
                unsigned int bh[4], bl[4];
                ldm4t(bh, a);
                ldm4t(bl, a + (VLO - VHI));
                mma16816(oacc[2 * j2],     pah[kk], bh);
                mma16816(oacc[2 * j2],     pah[kk], bl);
                mma16816(oacc[2 * j2],     pal[kk], bh);
                mma16816(oacc[2 * j2 + 1], pah[kk], bh + 2);
                mma16816(oacc[2 * j2 + 1], pah[kk], bl + 2);
                mma16816(oacc[2 * j2 + 1], pal[kk], bh + 2);
            }
        }
        __syncthreads();
    }

    l0 += __shfl_xor_sync(0xffffffffu, l0, 1);
    l0 += __shfl_xor_sync(0xffffffffu, l0, 2);
    l1 += __shfl_xor_sync(0xffffffffu, l1, 1);
    l1 += __shfl_xor_sync(0xffffffffu, l1, 2);
    const float i0 = (l0 > 0.f) ? 1.f / l0 : 0.f;
    const float i1 = (l1 > 0.f) ? 1.f / l1 : 0.f;

    float* os = reinterpret_cast<float*>(sm);
    const int r0 = 16 * w + rowA;
    #pragma unroll
    for (int j = 0; j < 16; j++) {
        const int c = 8 * j + 2 * qd;
        os[r0 * 132 + c]           = oacc[j][0] * i0;
        os[r0 * 132 + c + 1]       = oacc[j][1] * i0;
        os[(r0 + 8) * 132 + c]     = oacc[j][2] * i1;
        os[(r0 + 8) * 132 + c + 1] = oacc[j][3] * i1;
    }
    __syncthreads();
    float* og = out + ((size_t)(b * LL + qt * 128)) * DD;
    for (int i = tid; i < 128 * 32; i += 256) {
        const int r = i >> 5, j = i & 31;
        *reinterpret_cast<float4*>(og + r * 128 + 4 * j) =
            *reinterpret_cast<const float4*>(os + r * 132 + 4 * j);
    }
}

// ---------------------------------------------------------------------------
// Launch
// ---------------------------------------------------------------------------
extern "C" void kernel_launch(void* const* d_in, const int* in_sizes, int n_in,
                              void* d_out, int out_size)
{
    const float* Q    = (const float*)d_in[0];
    const float* K    = (const float*)d_in[1];
    const float* V    = (const float*)d_in[2];
    const int*   mask = (const int*)  d_in[3];
    const float* WQ   = (const float*)d_in[4];
    const float* WK   = (const float*)d_in[5];
    const float* WV   = (const float*)d_in[6];
    float* out = (float*)d_out;

    cudaFuncSetAttribute(proj_mma_kernel, cudaFuncAttributeMaxDynamicSharedMemorySize, P_SMEM);
    cudaFuncSetAttribute(attn_kernel, cudaFuncAttributeMaxDynamicSharedMemorySize, SMEM_BYTES);

    wconv_kernel<<<3 * 65536 / 256, 256>>>(WQ, WK, WV);
    proj_mma_kernel<<<dim3(128, 3), 256, P_SMEM>>>(Q, K, V);
    attn_kernel<<<dim3(32, BB), 256, SMEM_BYTES>>>(mask, out);
}

// round 9
// speedup vs baseline: 9.6470x; 1.5718x over previous
#include <cuda_runtime.h>
#include <cuda_bf16.h>
#include <math_constants.h>

#define BB 4
#define LL 4096
#define DM 1024
#define DD 128
#define SCALE 0.08838834764831845f

// ---------------- static device scratch (packed bf16 hi/lo pairs) -----------
__device__ unsigned int q_hi[BB * LL * 64], q_lo[BB * LL * 64];
__device__ unsigned int k_hi[BB * LL * 64], k_lo[BB * LL * 64];
__device__ unsigned int v_hi[BB * LL * 64], v_lo[BB * LL * 64];
__device__ unsigned int wt_hi[3 * 128 * 512], wt_lo[3 * 128 * 512];  // W^T packed

// ---------------- helpers ---------------------------------------------------
__device__ __forceinline__ unsigned int smem_u32(const void* p) {
    unsigned int a;
    asm("{ .reg .u64 t; cvta.to.shared.u64 t, %1; cvt.u32.u64 %0, t; }" : "=r"(a) : "l"(p));
    return a;
}
__device__ __forceinline__ unsigned int pk2(float a, float b) {
    __nv_bfloat162 t = __floats2bfloat162_rn(a, b);
    return *reinterpret_cast<unsigned int*>(&t);
}
__device__ __forceinline__ void split2(float a, float b, unsigned int& h, unsigned int& l) {
    __nv_bfloat16 ah = __float2bfloat16(a), bh = __float2bfloat16(b);
    h = ((unsigned int)__bfloat16_as_ushort(bh) << 16) | __bfloat16_as_ushort(ah);
    l = pk2(a - __bfloat162float(ah), b - __bfloat162float(bh));
}
__device__ __forceinline__ void ldm4(unsigned int* r, unsigned int a) {
    asm volatile("ldmatrix.sync.aligned.m8n8.x4.shared.b16 {%0,%1,%2,%3}, [%4];"
                 : "=r"(r[0]), "=r"(r[1]), "=r"(r[2]), "=r"(r[3]) : "r"(a));
}
__device__ __forceinline__ void ldm4t(unsigned int* r, unsigned int a) {
    asm volatile("ldmatrix.sync.aligned.m8n8.x4.trans.shared.b16 {%0,%1,%2,%3}, [%4];"
                 : "=r"(r[0]), "=r"(r[1]), "=r"(r[2]), "=r"(r[3]) : "r"(a));
}
__device__ __forceinline__ void mma16816(float* d, const unsigned int* a, const unsigned int* b) {
    asm volatile("mma.sync.aligned.m16n8k16.row.col.f32.bf16.bf16.f32 "
                 "{%0,%1,%2,%3}, {%4,%5,%6,%7}, {%8,%9}, {%0,%1,%2,%3};"
                 : "+f"(d[0]), "+f"(d[1]), "+f"(d[2]), "+f"(d[3])
                 : "r"(a[0]), "r"(a[1]), "r"(a[2]), "r"(a[3]), "r"(b[0]), "r"(b[1]));
}
__device__ __forceinline__ void cpa16(unsigned int dst, const void* src) {
    asm volatile("cp.async.cg.shared.global [%0], [%1], 16;" :: "r"(dst), "l"(src));
}
__device__ __forceinline__ void cpa_commit() {
    asm volatile("cp.async.commit_group;" ::: "memory");
}
__device__ __forceinline__ void cpa_wait1() {
    asm volatile("cp.async.wait_group 1;" ::: "memory");
}
__device__ __forceinline__ void cpa_wait0() {
    asm volatile("cp.async.wait_group 0;" ::: "memory");
}

// ---------------------------------------------------------------------------
// W^T pack: W[k][n] fp32 -> wt[n][kpair] bf16 hi/lo
// ---------------------------------------------------------------------------
__global__ __launch_bounds__(256)
void wconv_kernel(const float* __restrict__ WQ, const float* __restrict__ WK,
                  const float* __restrict__ WV)
{
    const int gid = blockIdx.x * 256 + threadIdx.x;      // < 3*65536
    const int t = gid >> 16, i = gid & 65535;
    const int n = i & 127, kp = i >> 7;
    const float* W = (t == 0) ? WQ : (t == 1) ? WK : WV;
    unsigned int h, l;
    split2(W[(2 * kp) * 128 + n], W[(2 * kp + 1) * 128 + n], h, l);
    wt_hi[t * 65536 + n * 512 + kp] = h;
    wt_lo[t * 65536 + n * 512 + kp] = l;
}

// ---------------------------------------------------------------------------
// Projection via mma.sync bf16x3, software pipelined.
// X chunk in registers (LDG prefetch), W via cp.async, both smem double-buffered.
// smem: X bufs @ 0 / 36864 (hi + lo planes of 18432 each)
//       W bufs @ 73728 / 110592
// ---------------------------------------------------------------------------
#define P_SMEM 147456

__global__ __launch_bounds__(256)
void proj_mma_kernel(const float* __restrict__ Qx, const float* __restrict__ Kx,
                     const float* __restrict__ Vx)
{
    extern __shared__ char sm[];
    const unsigned int sb = smem_u32(sm);
    const int tid = threadIdx.x, w = tid >> 5, lane = tid & 31;
    const int lr = lane & 7, g = lane >> 3, qd = lane & 3, rowA = lane >> 2;
    const int mt = blockIdx.x, t = blockIdx.y;

    const float2* Xp = reinterpret_cast<const float2*>(
        (t == 0) ? Qx : (t == 1) ? Kx : Vx);
    const unsigned int* WH = wt_hi + t * 65536;
    const unsigned int* WL = wt_lo + t * 65536;
    unsigned int* OH = (t == 0) ? q_hi : (t == 1) ? k_hi : v_hi;
    unsigned int* OL = (t == 0) ? q_lo : (t == 1) ? k_lo : v_lo;

    const int row0 = mt * 128;
    float acc[16][4] = {};
    float2 xr[16];

    // chunk c covers K pairs [c*32, c*32+32)
    #define LOADX(c)                                                          \
        _Pragma("unroll")                                                     \
        for (int u = 0; u < 16; u++) {                                        \
            const int i = tid + 256 * u;                                      \
            const int r = i >> 5, p = i & 31;                                 \
            xr[u] = Xp[(size_t)(row0 + r) * 512 + ((c) << 5) + p];            \
        }
    #define STOREX(base)                                                      \
        _Pragma("unroll")                                                     \
        for (int u = 0; u < 16; u++) {                                        \
            const int i = tid + 256 * u;                                      \
            const int r = i >> 5, p = i & 31;                                 \
            unsigned int h, l; split2(xr[u].x, xr[u].y, h, l);                \
            *reinterpret_cast<unsigned int*>(sm + (base) + r * 144 + p * 4) = h; \
            *reinterpret_cast<unsigned int*>(sm + (base) + 18432 + r * 144 + p * 4) = l; \
        }
    // 1024 cp.async per plane; 256 threads -> 4 iterations (i < 1024)
    #define ISSUEW(c, dstb)                                                   \
        _Pragma("unroll")                                                     \
        for (int u = 0; u < 4; u++) {                                         \
            const int i = tid + 256 * u;                                      \
            const int n = i >> 3, j = i & 7;                                  \
            const size_t gi = (size_t)n * 512 + ((c) << 5) + j * 4;           \
            cpa16((dstb) + n * 144 + j * 16, WH + gi);                        \
            cpa16((dstb) + 18432 + n * 144 + j * 16, WL + gi);                \
        }

    LOADX(0);
    STOREX(0);
    ISSUEW(0, sb + 73728);
    cpa_commit();

    for (int c = 0; c < 16; c++) {
        const int cur = c & 1, nxt = cur ^ 1;
        if (c < 15) {
            ISSUEW(c + 1, sb + 73728u + nxt * 36864u);
            cpa_commit();
            LOADX(c + 1);
            cpa_wait1();
        } else {
            cpa_wait0();
        }
        __syncthreads();

        const unsigned int xb = sb + cur * 36864u;
        const unsigned int wb = sb + 73728u + cur * 36864u;
        unsigned int ah[4][4], al[4][4];
        #pragma unroll
        for (int s = 0; s < 4; s++) {
            const int row = 16 * w + lr + ((g & 1) ? 8 : 0);
            const int col = 16 * s + ((g & 2) ? 8 : 0);
            const unsigned int a = xb + row * 144 + col * 2;
            ldm4(ah[s], a);
            ldm4(al[s], a + 18432);
        }
        #pragma unroll
        for (int s = 0; s < 4; s++) {
            #pragma unroll
            for (int j2 = 0; j2 < 8; j2++) {
                const int row = 16 * j2 + lr + ((g & 2) ? 8 : 0);
                const int col = 16 * s + ((g & 1) ? 8 : 0);
                const unsigned int a = wb + row * 144 + col * 2;
                unsigned int bh[4], bl[4];
                ldm4(bh, a);
                ldm4(bl, a + 18432);
                mma16816(acc[2 * j2],     ah[s], bh);
                mma16816(acc[2 * j2],     ah[s], bl);
                mma16816(acc[2 * j2],     al[s], bh);
                mma16816(acc[2 * j2 + 1], ah[s], bh + 2);
                mma16816(acc[2 * j2 + 1], ah[s], bl + 2);
                mma16816(acc[2 * j2 + 1], al[s], bh + 2);
            }
        }
        __syncthreads();
        if (c < 15) STOREX(nxt * 36864u);
    }

    const int r0 = row0 + 16 * w + rowA;
    #pragma unroll
    for (int j = 0; j < 16; j++) {
        const int pi = 4 * j + qd;
        unsigned int h, l;
        split2(acc[j][0], acc[j][1], h, l);
        OH[(size_t)r0 * 64 + pi] = h;
        OL[(size_t)r0 * 64 + pi] = l;
        split2(acc[j][2], acc[j][3], h, l);
        OH[(size_t)(r0 + 8) * 64 + pi] = h;
        OL[(size_t)(r0 + 8) * 64 + pi] = l;
    }
}

// ---------------------------------------------------------------------------
// Fused flash attention, cp.async double-buffered K/V (hi+lo both), bf16x3.
// smem: mask floats [0,16384); buffers @16384 + {0,69632}, each
//       KHI +0, KLO +17408, VHI +34816, VLO +52224 (64 rows x 272B per plane)
// ---------------------------------------------------------------------------
#define AB0 16384
#define ABUF 69632
#define SMEM_BYTES (16384 + 2 * 69632)

__global__ __launch_bounds__(256, 1)
void attn_kernel(const int* __restrict__ mask, float* __restrict__ out)
{
    extern __shared__ char sm[];
    const unsigned int sb = smem_u32(sm);
    const int tid = threadIdx.x, w = tid >> 5, lane = tid & 31;
    const int lr = lane & 7, g = lane >> 3, qd = lane & 3, rowA = lane >> 2;
    const int qt = blockIdx.x, b = blockIdx.y;

    // ---- stage mask (full row) + Q; fragment Q into registers ----
    float* mskf = reinterpret_cast<float*>(sm);
    for (int i = tid; i < LL; i += 256)
        mskf[i] = mask[b * LL + i] ? 0.f : -CUDART_INF_F;

    const unsigned int* qhs = q_hi + (size_t)(b * LL + qt * 128) * 64;
    const unsigned int* qls = q_lo + (size_t)(b * LL + qt * 128) * 64;
    for (int i = tid; i < 128 * 64; i += 256) {
        const int r = i >> 6, p = i & 63;
        *reinterpret_cast<unsigned int*>(sm + AB0 + r * 272 + p * 4) = qhs[i];
        *reinterpret_cast<unsigned int*>(sm + AB0 + 34816 + r * 272 + p * 4) = qls[i];
    }
    __syncthreads();
    unsigned int qh[8][4], ql[8][4];
    {
        const int row = 16 * w + lr + ((g & 1) ? 8 : 0);
        #pragma unroll
        for (int s = 0; s < 8; s++) {
            const int col = 16 * s + ((g & 2) ? 8 : 0);
            const unsigned int a = sb + AB0 + row * 272 + col * 2;
            ldm4(qh[s], a);
            ldm4(ql[s], a + 34816);
        }
    }
    __syncthreads();

    float oacc[16][4];
    #pragma unroll
    for (int j = 0; j < 16; j++)
        { oacc[j][0] = 0.f; oacc[j][1] = 0.f; oacc[j][2] = 0.f; oacc[j][3] = 0.f; }
    float m0 = -CUDART_INF_F, m1 = -CUDART_INF_F, l0 = 0.f, l1 = 0.f;

    const uint4* khi4 = reinterpret_cast<const uint4*>(k_hi) + (size_t)b * LL * 16;
    const uint4* klo4 = reinterpret_cast<const uint4*>(k_lo) + (size_t)b * LL * 16;
    const uint4* vhi4 = reinterpret_cast<const uint4*>(v_hi) + (size_t)b * LL * 16;
    const uint4* vlo4 = reinterpret_cast<const uint4*>(v_lo) + (size_t)b * LL * 16;

    #define ISSUE_TILE(kt, dstb)                                              \
        _Pragma("unroll")                                                     \
        for (int u = 0; u < 4; u++) {                                         \
            const int i = tid + 256 * u;                                      \
            const int key = i >> 4, j = i & 15;                               \
            const size_t gi = (size_t)((kt) * 64 + key) * 16 + j;             \
            const unsigned int so = key * 272 + j * 16;                       \
            cpa16((dstb) + so,         khi4 + gi);                            \
            cpa16((dstb) + 17408 + so, klo4 + gi);                            \
            cpa16((dstb) + 34816 + so, vhi4 + gi);                            \
            cpa16((dstb) + 52224 + so, vlo4 + gi);                            \
        }

    ISSUE_TILE(0, sb + AB0);
    cpa_commit();

    for (int kt = 0; kt < 64; kt++) {
        const unsigned int curb = sb + AB0 + (kt & 1) * ABUF;
        if (kt < 63) {
            ISSUE_TILE(kt + 1, sb + AB0 + ((kt + 1) & 1) * ABUF);
            cpa_commit();
            cpa_wait1();
        } else {
            cpa_wait0();
        }
        __syncthreads();

        // ---- S = Q . K^T (bf16x3) ----
        float sacc[8][4];
        #pragma unroll
        for (int j = 0; j < 8; j++)
            { sacc[j][0] = 0.f; sacc[j][1] = 0.f; sacc[j][2] = 0.f; sacc[j][3] = 0.f; }
        #pragma unroll
        for (int s = 0; s < 8; s++) {
            #pragma unroll
            for (int j2 = 0; j2 < 4; j2++) {
                const int row = 16 * j2 + lr + ((g & 2) ? 8 : 0);
                const int col = 16 * s + ((g & 1) ? 8 : 0);
                const unsigned int a = curb + row * 272 + col * 2;
                unsigned int bh[4], bl[4];
                ldm4(bh, a);
                ldm4(bl, a + 17408);
                mma16816(sacc[2 * j2],     qh[s], bh);
                mma16816(sacc[2 * j2],     qh[s], bl);
                mma16816(sacc[2 * j2],     ql[s], bh);
                mma16816(sacc[2 * j2 + 1], qh[s], bh + 2);
                mma16816(sacc[2 * j2 + 1], qh[s], bl + 2);
                mma16816(sacc[2 * j2 + 1], ql[s], bh + 2);
            }
        }

        // ---- mask + scale + online softmax ----
        const float* mt = mskf + kt * 64;
        float t0 = -CUDART_INF_F, t1 = -CUDART_INF_F;
        #pragma unroll
        for (int j = 0; j < 8; j++) {
            const float ma = mt[8 * j + 2 * qd], mb = mt[8 * j + 2 * qd + 1];
            sacc[j][0] = sacc[j][0] * SCALE + ma;
            sacc[j][1] = sacc[j][1] * SCALE + mb;
            sacc[j][2] = sacc[j][2] * SCALE + ma;
            sacc[j][3] = sacc[j][3] * SCALE + mb;
            t0 = fmaxf(t0, fmaxf(sacc[j][0], sacc[j][1]));
            t1 = fmaxf(t1, fmaxf(sacc[j][2], sacc[j][3]));
        }
        t0 = fmaxf(t0, __shfl_xor_sync(0xffffffffu, t0, 1));
        t0 = fmaxf(t0, __shfl_xor_sync(0xffffffffu, t0, 2));
        t1 = fmaxf(t1, __shfl_xor_sync(0xffffffffu, t1, 1));
        t1 = fmaxf(t1, __shfl_xor_sync(0xffffffffu, t1, 2));
        const float mn0 = fmaxf(m0, t0), mn1 = fmaxf(m1, t1);
        const float ms0 = (mn0 == -CUDART_INF_F) ? 0.f : mn0;
        const float ms1 = (mn1 == -CUDART_INF_F) ? 0.f : mn1;
        const float c0 = __expf(m0 - ms0), c1 = __expf(m1 - ms1);
        m0 = mn0; m1 = mn1;
        float rs0 = 0.f, rs1 = 0.f;
        #pragma unroll
        for (int j = 0; j < 8; j++) {
            sacc[j][0] = __expf(sacc[j][0] - ms0); rs0 += sacc[j][0];
            sacc[j][1] = __expf(sacc[j][1] - ms0); rs0 += sacc[j][1];
            sacc[j][2] = __expf(sacc[j][2] - ms1); rs1 += sacc[j][2];
            sacc[j][3] = __expf(sacc[j][3] - ms1); rs1 += sacc[j][3];
        }
        l0 = l0 * c0 + rs0;
        l1 = l1 * c1 + rs1;
        #pragma unroll
        for (int j = 0; j < 16; j++) {
            oacc[j][0] *= c0; oacc[j][1] *= c0;
            oacc[j][2] *= c1; oacc[j][3] *= c1;
        }

        // ---- P fragments (bf16 hi/lo) straight from S fragments ----
        unsigned int pah[4][4], pal[4][4];
        #pragma unroll
        for (int kk = 0; kk < 4; kk++) {
            split2(sacc[2 * kk][0],     sacc[2 * kk][1],     pah[kk][0], pal[kk][0]);
            split2(sacc[2 * kk][2],     sacc[2 * kk][3],     pah[kk][1], pal[kk][1]);
            split2(sacc[2 * kk + 1][0], sacc[2 * kk + 1][1], pah[kk][2], pal[kk][2]);
            split2(sacc[2 * kk + 1][2], sacc[2 * kk + 1][3], pah[kk][3], pal[kk][3]);
        }

        // ---- O += P . V  (bf16x3: Phi.Vhi + Phi.Vlo + Plo.Vhi) ----
        #pragma unroll
        for (int kk = 0; kk < 4; kk++) {
            #pragma unroll
            for (int j2 = 0; j2 < 8; j2++) {
                const int row = 16 * kk + lr + ((g & 1) ? 8 : 0);
                const int col = 16 * j2 + ((g & 2) ? 8 : 0);
                const unsigned int a = curb + 34816 + row * 272 + col * 2;
                unsigned int bh[4], bl[4];
                ldm4t(bh, a);
                ldm4t(bl, a + 17408);
                mma16816(oacc[2 * j2],     pah[kk], bh);
                mma16816(oacc[2 * j2],     pah[kk], bl);
                mma16816(oacc[2 * j2],     pal[kk], bh);
                mma16816(oacc[2 * j2 + 1], pah[kk], bh + 2);
                mma16816(oacc[2 * j2 + 1], pah[kk], bl + 2);
                mma16816(oacc[2 * j2 + 1], pal[kk], bh + 2);
            }
        }
        __syncthreads();
    }

    // ---- epilogue ----
    l0 += __shfl_xor_sync(0xffffffffu, l0, 1);
    l0 += __shfl_xor_sync(0xffffffffu, l0, 2);
    l1 += __shfl_xor_sync(0xffffffffu, l1, 1);
    l1 += __shfl_xor_sync(0xffffffffu, l1, 2);
    const float i0 = (l0 > 0.f) ? 1.f / l0 : 0.f;
    const float i1 = (l1 > 0.f) ? 1.f / l1 : 0.f;

    float* os = reinterpret_cast<float*>(sm + AB0);
    const int r0 = 16 * w + rowA;
    #pragma unroll
    for (int j = 0; j < 16; j++) {
        const int c = 8 * j + 2 * qd;
        os[r0 * 132 + c]           = oacc[j][0] * i0;
        os[r0 * 132 + c + 1]       = oacc[j][1] * i0;
        os[(r0 + 8) * 132 + c]     = oacc[j][2] * i1;
        os[(r0 + 8) * 132 + c + 1] = oacc[j][3] * i1;
    }
    __syncthreads();
    float* og = out + ((size_t)(b * LL + qt * 128)) * DD;
    for (int i = tid; i < 128 * 32; i += 256) {
        const int r = i >> 5, j = i & 31;
        *reinterpret_cast<float4*>(og + r * 128 + 4 * j) =
            *reinterpret_cast<const float4*>(os + r * 132 + 4 * j);
    }
}

// ---------------------------------------------------------------------------
// Launch
// ---------------------------------------------------------------------------
extern "C" void kernel_launch(void* const* d_in, const int* in_sizes, int n_in,
                              void* d_out, int out_size)
{
    const float* Q    = (const float*)d_in[0];
    const float* K    = (const float*)d_in[1];
    const float* V    = (const float*)d_in[2];
    const int*   mask = (const int*)  d_in[3];
    const float* WQ   = (const float*)d_in[4];
    const float* WK   = (const float*)d_in[5];
    const float* WV   = (const float*)d_in[6];
    float* out = (float*)d_out;

    cudaFuncSetAttribute(proj_mma_kernel, cudaFuncAttributeMaxDynamicSharedMemorySize, P_SMEM);
    cudaFuncSetAttribute(attn_kernel, cudaFuncAttributeMaxDynamicSharedMemorySize, SMEM_BYTES);

    wconv_kernel<<<3 * 65536 / 256, 256>>>(WQ, WK, WV);
    proj_mma_kernel<<<dim3(128, 3), 256, P_SMEM>>>(Q, K, V);
    attn_kernel<<<dim3(32, BB), 256, SMEM_BYTES>>>(mask, out);
}